// round 1
// baseline (speedup 1.0000x reference)
#include <cuda_runtime.h>

#define N_NEURONS 131072
#define NSTATES   32
#define CDIM      16
#define NBATCH    4
#define X_ELEMS   (NBATCH * N_NEURONS * NSTATES)   // 16777216
#define S_ELEMS   (N_NEURONS * NSTATES)            // 4194304
#define TPB       256
#define S_BLOCKS  (N_NEURONS / TPB)                // 512
#define GRID      (3 * S_BLOCKS)                   // 1536: 512 states + 1024 tanh

// ---------------- accurate fast tanh ----------------
// Odd Taylor series of tanh, valid (rel err < ~5e-5) for |x| <= 0.78.
__device__ __forceinline__ float tanh_poly(float x) {
    float t = x * x;
    float p = fmaf(t, -0.001455834387f, 0.003592128037f);
    p = fmaf(t, p, -0.008863235530f);
    p = fmaf(t, p,  0.021869488537f);
    p = fmaf(t, p, -0.053968253968f);
    p = fmaf(t, p,  0.133333333333f);
    p = fmaf(t, p, -0.333333333333f);
    p = fmaf(t, p,  1.0f);
    return x * p;
}

// Full-range tanh: exp2-based for |x| >= 0.77 (no cancellation there since
// tanh >= 0.64), Taylor poly below. rel err < ~5e-5 everywhere.
__device__ __forceinline__ float tanh_full(float x) {
    float r = fabsf(x);
    float e;
    asm("ex2.approx.ftz.f32 %0, %1;" : "=f"(e) : "f"(r * 2.8853900817779268f)); // exp(2r)
    float rc;
    asm("rcp.approx.ftz.f32 %0, %1;" : "=f"(rc) : "f"(e + 1.0f));
    float tb = fmaf(-2.0f, rc, 1.0f);          // 1 - 2/(e^{2r}+1) = tanh(r)
    tb = copysignf(tb, x);
    float tp = tanh_poly(x);
    return (r < 0.77f) ? tp : tb;
}

// tanh applied 4x. Stage-2 input is in (-1,1) (needs full range); stage-3
// input <= tanh(1)=0.7616, stage-4 input <= tanh(0.7616)=0.642 -> poly only.
__device__ __forceinline__ float tanh4(float x) {
    float y = tanh_full(x);
    y = tanh_full(y);
    y = tanh_poly(y);
    y = tanh_poly(y);
    return y;
}

// ---------------- fused kernel ----------------
__global__ void __launch_bounds__(TPB)
enn_kernel(const float* __restrict__ x,
           const float* __restrict__ ns,
           const float* __restrict__ Wenc,
           const float* __restrict__ benc,
           const float* __restrict__ Wdec,
           const float* __restrict__ bdec,
           float* __restrict__ xout,
           float* __restrict__ sout)
{
    const int bid = blockIdx.x;
    const int t   = threadIdx.x;

    if (bid % 3 == 0) {
        // =================== states path: one thread per neuron ===================
        if (!sout) return;
        __shared__ __align__(16) float sWenc[CDIM * NSTATES];
        __shared__ __align__(16) float sWdec[NSTATES * CDIM];
        __shared__ float sbenc[CDIM];
        __shared__ float sbdec[NSTATES];
        for (int i = t; i < CDIM * NSTATES; i += TPB) { sWenc[i] = Wenc[i]; sWdec[i] = Wdec[i]; }
        if (t < CDIM)    sbenc[t] = benc[t];
        if (t < NSTATES) sbdec[t] = bdec[t];
        __syncthreads();

        const int n = (bid / 3) * TPB + t;

        float st[NSTATES];
        float acc[NSTATES];
        {
            const float4* src = reinterpret_cast<const float4*>(ns) + (size_t)n * (NSTATES / 4);
            #pragma unroll
            for (int i = 0; i < NSTATES / 4; i++) {
                float4 v = src[i];
                st[4*i+0] = v.x; st[4*i+1] = v.y; st[4*i+2] = v.z; st[4*i+3] = v.w;
            }
            #pragma unroll
            for (int s = 0; s < NSTATES; s++) acc[s] = 0.0f;
        }

        #pragma unroll 1
        for (int L = 0; L < 4; L++) {
            // 1/sum_{i=0..L} 0.7^i
            const float winv = (L == 0) ? 1.0f
                             : (L == 1) ? (1.0f / 1.7f)
                             : (L == 2) ? (1.0f / 2.19f)
                             :            (1.0f / 2.533f);

            // sparsify, decay, push into running recency-weighted sum, average
            #pragma unroll
            for (int s = 0; s < NSTATES; s++) {
                float v = st[s];
                v = (fabsf(v) >= 0.01f) ? v : 0.0f;
                v *= 0.9f;
                acc[s] = fmaf(acc[s], 0.7f, v);
                st[s]  = acc[s] * winv;
            }

            // encoder: h = relu(st @ Wenc^T + benc)
            float h[CDIM];
            #pragma unroll
            for (int j = 0; j < CDIM; j++) {
                float a = sbenc[j];
                const float4* w4 = reinterpret_cast<const float4*>(&sWenc[j * NSTATES]);
                #pragma unroll
                for (int s4 = 0; s4 < NSTATES / 4; s4++) {
                    float4 w = w4[s4];
                    a = fmaf(w.x, st[4*s4+0], a);
                    a = fmaf(w.y, st[4*s4+1], a);
                    a = fmaf(w.z, st[4*s4+2], a);
                    a = fmaf(w.w, st[4*s4+3], a);
                }
                h[j] = fmaxf(a, 0.0f);
            }

            // decoder + importance threshold
            #pragma unroll
            for (int s = 0; s < NSTATES; s++) {
                float a = sbdec[s];
                const float4* w4 = reinterpret_cast<const float4*>(&sWdec[s * CDIM]);
                #pragma unroll
                for (int j4 = 0; j4 < CDIM / 4; j4++) {
                    float4 w = w4[j4];
                    a = fmaf(w.x, h[4*j4+0], a);
                    a = fmaf(w.y, h[4*j4+1], a);
                    a = fmaf(w.z, h[4*j4+2], a);
                    a = fmaf(w.w, h[4*j4+3], a);
                }
                st[s] = (fabsf(a) >= 0.05f) ? a : 0.0f;
            }

            // kth (8th) largest of |st|: 8-reg multiset, t8[0] = current min
            float t8[8];
            #pragma unroll
            for (int i = 0; i < 8; i++) t8[i] = fabsf(st[i]);
            #pragma unroll
            for (int i = 1; i < 8; i++) {
                float lo = fminf(t8[0], t8[i]);
                t8[i] = fmaxf(t8[0], t8[i]);
                t8[0] = lo;
            }
            #pragma unroll
            for (int i = 8; i < NSTATES; i++) {
                float v = fabsf(st[i]);
                t8[0] = fmaxf(t8[0], v);        // evict current min if v larger
                #pragma unroll
                for (int j = 1; j < 8; j++) {   // restore min at t8[0]
                    float lo = fminf(t8[0], t8[j]);
                    t8[j] = fmaxf(t8[0], t8[j]);
                    t8[0] = lo;
                }
            }
            const float kth = t8[0];
            #pragma unroll
            for (int s = 0; s < NSTATES; s++)
                st[s] = (fabsf(st[s]) >= kth) ? st[s] : 0.0f;
        }

        {
            float4* dst = reinterpret_cast<float4*>(sout) + (size_t)n * (NSTATES / 4);
            #pragma unroll
            for (int i = 0; i < NSTATES / 4; i++) {
                float4 v;
                v.x = st[4*i+0]; v.y = st[4*i+1]; v.z = st[4*i+2]; v.w = st[4*i+3];
                dst[i] = v;
            }
        }
    } else {
        // =================== x path: tanh^4 elementwise, float4 grid-stride ===================
        if (!xout) return;
        const int tb     = bid - bid / 3 - 1;           // 0 .. 2*S_BLOCKS-1
        const int idx    = tb * TPB + t;
        const int stride = 2 * S_BLOCKS * TPB;
        const float4* xin = reinterpret_cast<const float4*>(x);
        float4*       xo  = reinterpret_cast<float4*>(xout);
        #pragma unroll 2
        for (int i = idx; i < X_ELEMS / 4; i += stride) {
            float4 v = xin[i];
            v.x = tanh4(v.x);
            v.y = tanh4(v.y);
            v.z = tanh4(v.z);
            v.w = tanh4(v.w);
            xo[i] = v;
        }
    }
}

extern "C" void kernel_launch(void* const* d_in, const int* in_sizes, int n_in,
                              void* d_out, int out_size) {
    const float* x    = (const float*)d_in[0];
    const float* ns   = (const float*)d_in[1];
    const float* Wenc = (const float*)d_in[2];
    const float* benc = (const float*)d_in[3];
    const float* Wdec = (const float*)d_in[4];
    const float* bdec = (const float*)d_in[5];

    float* out  = (float*)d_out;
    float* xout = nullptr;
    float* sout = nullptr;
    if (out_size >= X_ELEMS + S_ELEMS) { xout = out; sout = out + X_ELEMS; }
    else if (out_size == S_ELEMS)      { sout = out; }
    else                               { xout = out; }

    enn_kernel<<<GRID, TPB>>>(x, ns, Wenc, benc, Wdec, bdec, xout, sout);
}

// round 2
// speedup vs baseline: 1.2239x; 1.2239x over previous
#include <cuda_runtime.h>

#define N_NEURONS 131072
#define NSTATES   32
#define CDIM      16
#define NBATCH    4
#define X_ELEMS   (NBATCH * N_NEURONS * NSTATES)   // 16777216
#define S_ELEMS   (N_NEURONS * NSTATES)            // 4194304
#define TPB       256

typedef unsigned long long u64;

// ---------------- f32x2 packed helpers (FFMA2 path, ptxas never emits these) ----
__device__ __forceinline__ u64 pack2(float a, float b) {
    u64 r; asm("mov.b64 %0, {%1, %2};" : "=l"(r) : "f"(a), "f"(b)); return r;
}
__device__ __forceinline__ float2 unpack2(u64 v) {
    float2 f; asm("mov.b64 {%0, %1}, %2;" : "=f"(f.x), "=f"(f.y) : "l"(v)); return f;
}
__device__ __forceinline__ u64 fma2(u64 a, u64 b, u64 c) {
    u64 d; asm("fma.rn.f32x2 %0, %1, %2, %3;" : "=l"(d) : "l"(a), "l"(b), "l"(c)); return d;
}
__device__ __forceinline__ u64 mul2(u64 a, u64 b) {
    u64 d; asm("mul.rn.f32x2 %0, %1, %2;" : "=l"(d) : "l"(a), "l"(b)); return d;
}

// ---------------- tanh pieces ----------------
// Packed odd-Taylor tanh poly, valid (rel err < ~2e-5) for |x| <= 0.78.
// C[0..7] = packed coeffs high->low (C[7] = 1.0).
__device__ __forceinline__ u64 poly2(u64 x2, const u64* __restrict__ C) {
    u64 t2 = mul2(x2, x2);
    u64 p  = fma2(t2, C[0], C[1]);
    p = fma2(t2, p, C[2]);
    p = fma2(t2, p, C[3]);
    p = fma2(t2, p, C[4]);
    p = fma2(t2, p, C[5]);
    p = fma2(t2, p, C[6]);
    p = fma2(t2, p, C[7]);
    return mul2(p, x2);
}

__device__ __forceinline__ void make_coeffs(u64* C) {
    const float c[8] = { -0.001455834387f,  0.003592128037f, -0.008863235530f,
                          0.021869488537f, -0.053968253968f,  0.133333333333f,
                         -0.333333333333f,  1.0f };
    #pragma unroll
    for (int i = 0; i < 8; i++) C[i] = pack2(c[i], c[i]);
}

// exp-based branch for |x| >= 0.77 (tanh >= 0.64 there: no cancellation)
__device__ __forceinline__ float tanh_branch(float x) {
    float r = fabsf(x);
    float e;
    asm("ex2.approx.ftz.f32 %0, %1;" : "=f"(e) : "f"(r * 2.8853900817779268f));
    float rc;
    asm("rcp.approx.ftz.f32 %0, %1;" : "=f"(rc) : "f"(e + 1.0f));
    return copysignf(fmaf(-2.0f, rc, 1.0f), x);
}

// full-range tanh on a pair
__device__ __forceinline__ void tanh_full_pair(float& a, float& b, const u64* __restrict__ C) {
    const float xa = a, xb = b;
    float2 tp = unpack2(poly2(pack2(xa, xb), C));
    float tba = tanh_branch(xa);
    float tbb = tanh_branch(xb);
    a = (fabsf(xa) < 0.77f) ? tp.x : tba;
    b = (fabsf(xb) < 0.77f) ? tp.y : tbb;
}

// tanh applied 4x. Stage-3 input <= tanh(1)=0.7616 < 0.78, stage-4 input
// <= tanh(0.7616)=0.642 -> pure poly for last two stages.
__device__ __forceinline__ void tanh4_pair(float& a, float& b, const u64* __restrict__ C) {
    tanh_full_pair(a, b, C);
    tanh_full_pair(a, b, C);
    float2 f = unpack2(poly2(pack2(a, b), C)); a = f.x; b = f.y;
    f = unpack2(poly2(pack2(a, b), C));        a = f.x; b = f.y;
}

// =================== tanh kernel: x -> tanh^4(x), float4 x ILP4 ===================
#define TANH_GRID (X_ELEMS / 4 / (TPB * 4))   // 4096 blocks, exact cover

__global__ void __launch_bounds__(TPB, 3)
tanh_kernel(const float4* __restrict__ xin, float4* __restrict__ xout)
{
    u64 C[8];
    make_coeffs(C);

    const int base = blockIdx.x * (TPB * 4) + threadIdx.x;
    float4 v[4];
    #pragma unroll
    for (int k = 0; k < 4; k++) v[k] = xin[base + k * TPB];   // batched LDG.128 (MLP=4)

    #pragma unroll
    for (int k = 0; k < 4; k++) {
        tanh4_pair(v[k].x, v[k].y, C);
        tanh4_pair(v[k].z, v[k].w, C);
    }

    #pragma unroll
    for (int k = 0; k < 4; k++) xout[base + k * TPB] = v[k];
}

// =================== states kernel: one thread per neuron ===================
__global__ void __launch_bounds__(TPB)
states_kernel(const float* __restrict__ ns,
              const float* __restrict__ Wenc,
              const float* __restrict__ benc,
              const float* __restrict__ Wdec,
              const float* __restrict__ bdec,
              float* __restrict__ sout)
{
    __shared__ __align__(16) float sWenc[CDIM * NSTATES];
    __shared__ __align__(16) float sWdec[NSTATES * CDIM];
    __shared__ float sbenc[CDIM];
    __shared__ float sbdec[NSTATES];
    {
        const int t = threadIdx.x;
        for (int i = t; i < CDIM * NSTATES; i += TPB) { sWenc[i] = Wenc[i]; sWdec[i] = Wdec[i]; }
        if (t < CDIM)    sbenc[t] = benc[t];
        if (t < NSTATES) sbdec[t] = bdec[t];
    }
    __syncthreads();

    const int n = blockIdx.x * TPB + threadIdx.x;

    float st[NSTATES];
    float acc[NSTATES];
    {
        const float4* src = reinterpret_cast<const float4*>(ns) + (size_t)n * (NSTATES / 4);
        #pragma unroll
        for (int i = 0; i < NSTATES / 4; i++) {
            float4 v = src[i];
            st[4*i+0] = v.x; st[4*i+1] = v.y; st[4*i+2] = v.z; st[4*i+3] = v.w;
        }
        #pragma unroll
        for (int s = 0; s < NSTATES; s++) acc[s] = 0.0f;
    }

    #pragma unroll 1
    for (int L = 0; L < 4; L++) {
        // 1 / sum_{i=0..L} 0.7^i
        const float winv = (L == 0) ? 1.0f
                         : (L == 1) ? (1.0f / 1.7f)
                         : (L == 2) ? (1.0f / 2.19f)
                         :            (1.0f / 2.533f);

        // sparsify, decay, recency-weighted running sum, average
        #pragma unroll
        for (int s = 0; s < NSTATES; s++) {
            float v = st[s];
            v = (fabsf(v) >= 0.01f) ? v : 0.0f;
            v *= 0.9f;
            acc[s] = fmaf(acc[s], 0.7f, v);
            st[s]  = acc[s] * winv;
        }

        // pack states into f32x2 pairs for FFMA2 GEMMs
        u64 pst[NSTATES / 2];
        #pragma unroll
        for (int i = 0; i < NSTATES / 2; i++) pst[i] = pack2(st[2*i], st[2*i+1]);

        // encoder: h = relu(st @ Wenc^T + benc), 16 FFMA2 per output
        float h[CDIM];
        #pragma unroll
        for (int j = 0; j < CDIM; j++) {
            const u64* w2 = reinterpret_cast<const u64*>(&sWenc[j * NSTATES]);
            u64 a2 = pack2(sbenc[j], 0.0f);
            #pragma unroll
            for (int s2 = 0; s2 < NSTATES / 2; s2++) a2 = fma2(pst[s2], w2[s2], a2);
            float2 f = unpack2(a2);
            h[j] = fmaxf(f.x + f.y, 0.0f);
        }

        u64 ph[CDIM / 2];
        #pragma unroll
        for (int i = 0; i < CDIM / 2; i++) ph[i] = pack2(h[2*i], h[2*i+1]);

        // decoder + importance threshold, 8 FFMA2 per output
        #pragma unroll
        for (int s = 0; s < NSTATES; s++) {
            const u64* w2 = reinterpret_cast<const u64*>(&sWdec[s * CDIM]);
            u64 a2 = pack2(sbdec[s], 0.0f);
            #pragma unroll
            for (int j2 = 0; j2 < CDIM / 2; j2++) a2 = fma2(ph[j2], w2[j2], a2);
            float2 f = unpack2(a2);
            float a = f.x + f.y;
            st[s] = (fabsf(a) >= 0.05f) ? a : 0.0f;
        }

        // kth (8th) largest of |st|: 8-reg multiset with t8[0] = current min
        float t8[8];
        #pragma unroll
        for (int i = 0; i < 8; i++) t8[i] = fabsf(st[i]);
        #pragma unroll
        for (int i = 1; i < 8; i++) {
            float lo = fminf(t8[0], t8[i]);
            t8[i] = fmaxf(t8[0], t8[i]);
            t8[0] = lo;
        }
        #pragma unroll
        for (int i = 8; i < NSTATES; i++) {
            float v = fabsf(st[i]);
            t8[0] = fmaxf(t8[0], v);          // evict current min if v larger
            #pragma unroll
            for (int j = 1; j < 8; j++) {     // restore min at t8[0]
                float lo = fminf(t8[0], t8[j]);
                t8[j] = fmaxf(t8[0], t8[j]);
                t8[0] = lo;
            }
        }
        const float kth = t8[0];
        #pragma unroll
        for (int s = 0; s < NSTATES; s++)
            st[s] = (fabsf(st[s]) >= kth) ? st[s] : 0.0f;
    }

    {
        float4* dst = reinterpret_cast<float4*>(sout) + (size_t)n * (NSTATES / 4);
        #pragma unroll
        for (int i = 0; i < NSTATES / 4; i++) {
            float4 v;
            v.x = st[4*i+0]; v.y = st[4*i+1]; v.z = st[4*i+2]; v.w = st[4*i+3];
            dst[i] = v;
        }
    }
}

extern "C" void kernel_launch(void* const* d_in, const int* in_sizes, int n_in,
                              void* d_out, int out_size) {
    const float* x    = (const float*)d_in[0];
    const float* ns   = (const float*)d_in[1];
    const float* Wenc = (const float*)d_in[2];
    const float* benc = (const float*)d_in[3];
    const float* Wdec = (const float*)d_in[4];
    const float* bdec = (const float*)d_in[5];

    float* out  = (float*)d_out;
    float* xout = nullptr;
    float* sout = nullptr;
    if (out_size >= X_ELEMS + S_ELEMS) { xout = out; sout = out + X_ELEMS; }
    else if (out_size == S_ELEMS)      { sout = out; }
    else                               { xout = out; }

    if (xout)
        tanh_kernel<<<TANH_GRID, TPB>>>(reinterpret_cast<const float4*>(x),
                                        reinterpret_cast<float4*>(xout));
    if (sout)
        states_kernel<<<N_NEURONS / TPB, TPB>>>(ns, Wenc, benc, Wdec, bdec, sout);
}